// round 9
// baseline (speedup 1.0000x reference)
#include <cuda_runtime.h>
#include <math.h>

// ---------------- problem constants ----------------
#define B_    2
#define K_    384
#define N_    4096
#define D_    1024
#define H_    150
#define HP_   152
#define LRWP_ 384
#define L_    12
#define NB_   10
#define DE_   20

#define SZ_U   (B_*K_*D_)
#define SZ_P   (B_*K_*K_)
#define SZ_S   (B_*K_)

// ---------------- device scratch ----------------
__device__ float g_u[SZ_U];
__device__ float g_u2[SZ_U];
__device__ float g_ut[SZ_U];
__device__ float g_ut2[SZ_U];
__device__ float g_lr[B_*K_*LRWP_];
__device__ float g_wlr[D_*LRWP_];
__device__ float g_blr[LRWP_];
__device__ float g_dp[NB_*HP_];
__device__ float g_probs[2*SZ_P];
__device__ float g_inv[2*SZ_S];
__device__ float g_c[2*SZ_U];
__device__ float g_tmp[SZ_U];
__device__ float g_ctxt[SZ_U];
__device__ float g_wff1t[3*D_*D_];
__device__ float g_wff2t[D_*D_];
__device__ float g_wgt[2*D_*D_];

__device__ __forceinline__ unsigned f2t(float x) {
    unsigned r;
    asm("cvt.rna.tf32.f32 %0, %1;" : "=r"(r) : "f"(x));
    return r;
}
__device__ __forceinline__ float rna(float x) { return __uint_as_float(f2t(x)); }

__device__ __forceinline__ void cpa16(void* s, const void* g) {
    unsigned sa = (unsigned)__cvta_generic_to_shared(s);
    asm volatile("cp.async.cg.shared.global [%0], [%1], 16;" :: "r"(sa), "l"(g));
}
__device__ __forceinline__ void cp_commit() { asm volatile("cp.async.commit_group;"); }
template<int Nw>
__device__ __forceinline__ void cp_wait() { asm volatile("cp.async.wait_group %0;" :: "n"(Nw)); }

// ---------------- weight/input tf32 conversion ----------------
__global__ void convert_kernel(const float* __restrict__ Wff1,
                               const float* __restrict__ Wff2,
                               const float* __restrict__ Wg,
                               const float* __restrict__ span_vecs,
                               float* __restrict__ wff1t,
                               float* __restrict__ wff2t,
                               float* __restrict__ wgt,
                               float* __restrict__ u,
                               float* __restrict__ ut)
{
    int tid = blockIdx.x * blockDim.x + threadIdx.x;
    int nthr = gridDim.x * blockDim.x;
    for (int i = tid; i < 3*D_*D_; i += nthr) wff1t[i] = rna(Wff1[i]);
    for (int i = tid; i < D_*D_;   i += nthr) wff2t[i] = rna(Wff2[i]);
    for (int i = tid; i < 2*D_*D_; i += nthr) wgt[i]   = rna(Wg[i]);
    for (int i = tid; i < SZ_U; i += nthr) {
        float v = span_vecs[i];
        u[i] = v;
        ut[i] = rna(v);
    }
}

// ---------------- init: dp table + W_lr / b_lr concat ----------------
__global__ void init_kernel(const float* __restrict__ dist_emb,
                            const float* __restrict__ Wd,
                            const float* __restrict__ bd,
                            const float* __restrict__ Wl,
                            const float* __restrict__ bl,
                            const float* __restrict__ Wr,
                            const float* __restrict__ br,
                            float* __restrict__ dp,
                            float* __restrict__ wlr,
                            float* __restrict__ blr)
{
    int tid = blockIdx.x * blockDim.x + threadIdx.x;
    int nthr = gridDim.x * blockDim.x;
    for (int idx = tid; idx < NB_*HP_; idx += nthr) {
        int n = idx / HP_, h = idx % HP_;
        float v = 0.f;
        if (h < H_) {
            v = bd[h];
            #pragma unroll
            for (int t = 0; t < DE_; t++)
                v += dist_emb[n * DE_ + t] * Wd[t * H_ + h];
        }
        dp[idx] = v;
    }
    for (int idx = tid; idx < D_*LRWP_; idx += nthr) {
        int k = idx / LRWP_, c = idx % LRWP_;
        float v = 0.f;
        if (c < H_) v = Wl[k * H_ + c];
        else if (c >= HP_ && c < HP_ + H_) v = Wr[k * H_ + (c - HP_)];
        wlr[idx] = rna(v);
    }
    for (int c = tid; c < LRWP_; c += nthr) {
        float v = 0.f;
        if (c < H_) v = bl[c];
        else if (c >= HP_ && c < HP_ + H_) v = br[c - HP_];
        blr[c] = v;
    }
}

// ---------------- tf32 GEMM: 2 warps, warp tile 32x64 (A read once) ----------------
// 64 threads. Block tile BM x 64, warps split M. K-step 32, cp.async 3-stage.
#define ASTRIDE 36
#define BSTRIDE 72
template<int BM>
__global__ void __launch_bounds__(64, 4)
mma_gemm(const float* __restrict__ a0,
         const float* __restrict__ a1,
         const float* __restrict__ a2,
         const float* __restrict__ W,
         const float* __restrict__ bias,
         const float* __restrict__ rowscale,
         const float* __restrict__ e1,
         const float* __restrict__ e2,
         float* __restrict__ Cout,
         float* __restrict__ Ct,
         int M, int N, int K, int lda, int ldc,
         long sA, long sW, int bzmask, long sC, int sRS,
         int act, int roundOut)
{
    constexpr int MT = BM / 32;            // m16 tiles per warp (2 for 64, 1 for 32)
    constexpr int AIDS = BM * 32 / 4;      // cpa16 count for A tile
    constexpr int ASZ = BM * ASTRIDE;
    constexpr int BSZ = 32 * BSTRIDE;
    extern __shared__ unsigned dsm[];
    unsigned* Abase = dsm;
    unsigned* Bbase = dsm + 3 * ASZ;

    int z = blockIdx.z;
    a0 += (long)z * sA;
    W  += (long)(z & bzmask) * sW;
    Cout += (long)z * sC;
    if (rowscale) rowscale += (long)z * sRS;

    int tid = threadIdx.x;
    int warp = tid >> 5, lane = tid & 31;
    int m0 = blockIdx.y * BM, n0 = blockIdx.x * 64;
    int wm = warp * (BM / 2);

    auto issue = [&](int k0, int stage) {
        unsigned* As = Abase + stage * ASZ;
        unsigned* Bs = Bbase + stage * BSZ;
        int seg = k0 >> 10, col = k0 & 1023;
        const float* ap = (seg == 0) ? a0 : (seg == 1) ? a1 : a2;
        #pragma unroll
        for (int i = 0; i < AIDS / 64; i++) {
            int id = tid + i * 64;
            int row = id >> 3, c16 = (id & 7) * 4;
            cpa16(As + row * ASTRIDE + c16, ap + (long)(m0 + row) * lda + col + c16);
        }
        #pragma unroll
        for (int i = 0; i < 8; i++) {
            int id = tid + i * 64;
            int kr = id >> 4, c16 = (id & 15) * 4;
            cpa16(Bs + kr * BSTRIDE + c16, W + (long)(k0 + kr) * N + n0 + c16);
        }
        cp_commit();
    };

    int nt = K >> 5;
    issue(0, 0);
    issue(32, 1);

    float acc[MT][8][4];
    #pragma unroll
    for (int i = 0; i < MT; i++)
        #pragma unroll
        for (int j = 0; j < 8; j++)
            #pragma unroll
            for (int q = 0; q < 4; q++) acc[i][j][q] = 0.f;

    int stage = 0;
    for (int t = 0; t < nt; t++) {
        if (t == nt - 1) cp_wait<0>(); else cp_wait<1>();
        __syncthreads();
        if (t + 2 < nt) issue((t + 2) << 5, (stage + 2) % 3);

        unsigned* As = Abase + stage * ASZ;
        unsigned* Bs = Bbase + stage * BSZ;

        #pragma unroll
        for (int kx = 0; kx < 4; kx++) {
            unsigned a[MT][4];
            #pragma unroll
            for (int mt = 0; mt < MT; mt++) {
                int r_ = wm + mt * 16 + (lane >> 2);
                int c_ = kx * 8 + (lane & 3);
                a[mt][0] = As[r_ * ASTRIDE + c_];
                a[mt][1] = As[(r_ + 8) * ASTRIDE + c_];
                a[mt][2] = As[r_ * ASTRIDE + c_ + 4];
                a[mt][3] = As[(r_ + 8) * ASTRIDE + c_ + 4];
            }
            #pragma unroll
            for (int ct = 0; ct < 8; ct++) {
                unsigned b0 = Bs[(kx*8 + (lane & 3)) * BSTRIDE + ct*8 + (lane >> 2)];
                unsigned b1 = Bs[(kx*8 + (lane & 3) + 4) * BSTRIDE + ct*8 + (lane >> 2)];
                #pragma unroll
                for (int mt = 0; mt < MT; mt++) {
                    asm volatile(
                        "mma.sync.aligned.m16n8k8.row.col.f32.tf32.tf32.f32 "
                        "{%0,%1,%2,%3}, {%4,%5,%6,%7}, {%8,%9}, {%0,%1,%2,%3};"
                        : "+f"(acc[mt][ct][0]), "+f"(acc[mt][ct][1]),
                          "+f"(acc[mt][ct][2]), "+f"(acc[mt][ct][3])
                        : "r"(a[mt][0]), "r"(a[mt][1]), "r"(a[mt][2]), "r"(a[mt][3]),
                          "r"(b0), "r"(b1));
                }
            }
        }
        stage = (stage + 1) % 3;
    }

    #pragma unroll
    for (int mt = 0; mt < MT; mt++) {
        #pragma unroll
        for (int rh = 0; rh < 2; rh++) {
            int gm = m0 + wm + mt * 16 + (lane >> 2) + rh * 8;
            float rs = rowscale ? rowscale[gm] : 1.f;
            #pragma unroll
            for (int ct = 0; ct < 8; ct++) {
                int gn = n0 + ct * 8 + (lane & 3) * 2;
                float v0 = acc[mt][ct][rh * 2 + 0];
                float v1 = acc[mt][ct][rh * 2 + 1];
                if (bias) { v0 += bias[gn]; v1 += bias[gn + 1]; }
                v0 *= rs; v1 *= rs;
                long off = (long)gm * ldc + gn;
                if (act == 1) { v0 = tanhf(v0); v1 = tanhf(v1); }
                else if (act == 2) {
                    v0 = 1.f / (1.f + expf(-v0));
                    v1 = 1.f / (1.f + expf(-v1));
                }
                else if (act == 3) {
                    float g0 = 1.f / (1.f + expf(-v0));
                    float g1 = 1.f / (1.f + expf(-v1));
                    v0 = g0 * e1[off]     + (1.f - g0) * e2[off];
                    v1 = g1 * e1[off + 1] + (1.f - g1) * e2[off + 1];
                }
                if (roundOut) { v0 = rna(v0); v1 = rna(v1); }
                *(float2*)(Cout + off) = make_float2(v0, v1);
                if (Ct) *(float2*)(Ct + off) = make_float2(rna(v0), rna(v1));
            }
        }
    }
}

// ---------------- TC scorer v4: warp-private tiles, 4 acc chains, RMW prefetch ----------------
#define SCOR_HSTRIDE 156
#define SCOR_SMEM_WORDS (NB_*HP_ + 2*(2*19*32) + K_ + 16 + 8*16*SCOR_HSTRIDE)
__global__ void __launch_bounds__(256)
scorer_tc(const float* __restrict__ lr,
          const float* __restrict__ dp,
          const float* __restrict__ Wo,
          const float* __restrict__ bo,
          const int* __restrict__ span_begin,
          const int* __restrict__ span_end,
          float* __restrict__ scores,
          int first)
{
    extern __shared__ float sm[];
    float* s_t  = sm;                           // [NB][152]
    uint2* s_w2 = (uint2*)(sm + NB_*HP_);       // [2][19][32] of (w_k, w_k+4)
    int*   s_bk = (int*)(s_w2 + 2*19*32);       // [384]
    float* s_bo = (float*)(s_bk + K_);          // [16]
    float* s_h  = s_bo + 16;                    // [8][16][156]

    int i = blockIdx.x, b = blockIdx.y;
    int tid = threadIdx.x;
    int warp = tid >> 5, lane = tid & 31;

    const float* lrow = lr + (long)(b * K_ + i) * LRWP_;
    for (int x = tid; x < NB_ * HP_; x += 256)
        s_t[x] = rna(lrow[x % HP_] + dp[x]);

    for (int x = tid; x < 2 * 19 * 32; x += 256) {
        int ln = x & 31, kt = (x >> 5) % 19, nt = x / (19 * 32);
        int k0 = kt * 8 + (ln & 3), k1 = k0 + 4;
        int n  = nt * 8 + (ln >> 2);
        uint2 v;
        v.x = (k0 < H_ && n < L_) ? f2t(Wo[k0 * L_ + n]) : 0u;
        v.y = (k1 < H_ && n < L_) ? f2t(Wo[k1 * L_ + n]) : 0u;
        s_w2[x] = v;
    }

    int endi = span_end[b * K_ + i];
    for (int j = tid; j < K_; j += 256) {
        int d = span_begin[b * K_ + j] - endi;
        int da = d < 0 ? -d : d;
        int bk;
        if (da <= 4) bk = da;
        else {
            int lg = 31 - __clz(da) + 3;
            bk = lg < (NB_ - 1) ? lg : (NB_ - 1);
        }
        s_bk[j] = bk;
    }
    if (tid < 16) s_bo[tid] = (tid < L_) ? bo[tid] : 0.f;
    __syncthreads();

    float* hbase = s_h + warp * (16 * SCOR_HSTRIDE);
    const float* rbase = lr + (long)b * K_ * LRWP_ + HP_;
    int row = lane >> 1, half = lane & 1;
    int ar = lane >> 2, ac = lane & 3;
    long srow = (long)(b * K_ + i) * K_;
    int gc0 = (lane & 3) * 2;
    int gc1 = 8 + gc0;
    bool nt1ok = gc1 < L_;

    #pragma unroll
    for (int s = 0; s < 3; s++) {
        int j0 = (s * 8 + warp) * 16;

        // prefetch old scores for RMW (off the critical path)
        long o0 = (srow + j0 + ar) * L_ + gc0;
        float2 q00, q01, q10, q11;
        if (!first) {
            q00 = *(float2*)(scores + o0);
            q01 = *(float2*)(scores + o0 + 8 * L_);
            if (nt1ok) {
                q10 = *(float2*)(scores + o0 + 8);
                q11 = *(float2*)(scores + o0 + 8 * L_ + 8);
            }
        }

        // build private H tile
        {
            int j = j0 + row;
            const float* rr = rbase + (long)j * LRWP_ + half * 76;
            const float* tt = s_t + s_bk[j] * HP_ + half * 76;
            float* hh = hbase + row * SCOR_HSTRIDE + half * 76;
            #pragma unroll
            for (int x = 0; x < 19; x++) {
                float4 rv = *(const float4*)(rr + x * 4);
                float4 tv = *(const float4*)(tt + x * 4);
                float4 hv;
                hv.x = rna(fmaxf(rv.x + tv.x, 0.f));
                hv.y = rna(fmaxf(rv.y + tv.y, 0.f));
                hv.z = rna(fmaxf(rv.z + tv.z, 0.f));
                hv.w = rna(fmaxf(rv.w + tv.w, 0.f));
                *(float4*)(hh + x * 4) = hv;
            }
        }
        __syncwarp();

        // 4 independent accumulator chains (even/odd kt x 2 ntiles)
        float acc0[2][4] = {{0.f,0.f,0.f,0.f},{0.f,0.f,0.f,0.f}};
        float acc1[2][4] = {{0.f,0.f,0.f,0.f},{0.f,0.f,0.f,0.f}};
        #pragma unroll
        for (int kt = 0; kt < 19; kt++) {
            int p = kt & 1;
            unsigned a0 = __float_as_uint(hbase[ar * SCOR_HSTRIDE + kt * 8 + ac]);
            unsigned a1 = __float_as_uint(hbase[(ar + 8) * SCOR_HSTRIDE + kt * 8 + ac]);
            unsigned a2 = __float_as_uint(hbase[ar * SCOR_HSTRIDE + kt * 8 + ac + 4]);
            unsigned a3 = __float_as_uint(hbase[(ar + 8) * SCOR_HSTRIDE + kt * 8 + ac + 4]);
            uint2 w0 = s_w2[kt * 32 + lane];
            uint2 w1 = s_w2[(19 + kt) * 32 + lane];
            asm volatile(
                "mma.sync.aligned.m16n8k8.row.col.f32.tf32.tf32.f32 "
                "{%0,%1,%2,%3}, {%4,%5,%6,%7}, {%8,%9}, {%0,%1,%2,%3};"
                : "+f"(acc0[p][0]), "+f"(acc0[p][1]), "+f"(acc0[p][2]), "+f"(acc0[p][3])
                : "r"(a0), "r"(a1), "r"(a2), "r"(a3), "r"(w0.x), "r"(w0.y));
            asm volatile(
                "mma.sync.aligned.m16n8k8.row.col.f32.tf32.tf32.f32 "
                "{%0,%1,%2,%3}, {%4,%5,%6,%7}, {%8,%9}, {%0,%1,%2,%3};"
                : "+f"(acc1[p][0]), "+f"(acc1[p][1]), "+f"(acc1[p][2]), "+f"(acc1[p][3])
                : "r"(a0), "r"(a1), "r"(a2), "r"(a3), "r"(w1.x), "r"(w1.y));
        }

        // epilogue: ntile 0 (cols 0..7, all < 12)
        {
            float v0 = acc0[0][0] + acc0[1][0] + s_bo[gc0];
            float v1 = acc0[0][1] + acc0[1][1] + s_bo[gc0 + 1];
            float v2 = acc0[0][2] + acc0[1][2] + s_bo[gc0];
            float v3 = acc0[0][3] + acc0[1][3] + s_bo[gc0 + 1];
            if (!first) { v0 += q00.x; v1 += q00.y; v2 += q01.x; v3 += q01.y; }
            *(float2*)(scores + o0)          = make_float2(v0, v1);
            *(float2*)(scores + o0 + 8 * L_) = make_float2(v2, v3);
        }
        // ntile 1 (cols 8..11 valid)
        if (nt1ok) {
            float v0 = acc1[0][0] + acc1[1][0] + s_bo[gc1];
            float v1 = acc1[0][1] + acc1[1][1] + s_bo[gc1 + 1];
            float v2 = acc1[0][2] + acc1[1][2] + s_bo[gc1];
            float v3 = acc1[0][3] + acc1[1][3] + s_bo[gc1 + 1];
            if (!first) { v0 += q10.x; v1 += q10.y; v2 += q11.x; v3 += q11.y; }
            *(float2*)(scores + o0 + 8)          = make_float2(v0, v1);
            *(float2*)(scores + o0 + 8 * L_ + 8) = make_float2(v2, v3);
        }
        __syncwarp();
    }
}

// ---------------- probs + row-sums fused ----------------
__global__ void probs_kernel(const float* __restrict__ scores,
                             const float* __restrict__ mask,
                             float* __restrict__ probsAll,
                             float* __restrict__ invAll)
{
    int i = blockIdx.x, b = blockIdx.y;
    float ssum = 0.f;
    for (int j = threadIdx.x; j < K_; j += blockDim.x) {
        const float* s = scores + (((long)(b * K_ + i)) * K_ + j) * L_;
        float m = s[0];
        #pragma unroll
        for (int c = 1; c < L_; c++) m = fmaxf(m, s[c]);
        float p = rna((1.f / (1.f + expf(-m))) * mask[((long)(b * K_ + i)) * K_ + j]);
        probsAll[((long)(b * K_ + i)) * K_ + j] = p;
        probsAll[(long)SZ_P + ((long)(b * K_ + j)) * K_ + i] = p;
        ssum += p;
    }
    __shared__ float red[4];
    #pragma unroll
    for (int o = 16; o > 0; o >>= 1) ssum += __shfl_down_sync(0xffffffffu, ssum, o);
    int wid = threadIdx.x >> 5;
    if ((threadIdx.x & 31) == 0) red[wid] = ssum;
    __syncthreads();
    if (threadIdx.x == 0)
        invAll[b * K_ + i] = 1.f / (red[0] + red[1] + red[2] + red[3] + 1e-7f);
}

// ---------------- inverse column sums (probsT rows) ----------------
__global__ void invsum_kernel(const float* __restrict__ probsAll,
                              float* __restrict__ invAll)
{
    int row = blockIdx.x;
    const float* src = probsAll + (long)SZ_P + (long)row * K_;
    float s = 0.f;
    for (int j = threadIdx.x; j < K_; j += blockDim.x) s += src[j];
    __shared__ float red[4];
    #pragma unroll
    for (int o = 16; o > 0; o >>= 1) s += __shfl_down_sync(0xffffffffu, s, o);
    int wid = threadIdx.x >> 5;
    if ((threadIdx.x & 31) == 0) red[wid] = s;
    __syncthreads();
    if (threadIdx.x == 0)
        invAll[SZ_S + row] = 1.f / (red[0] + red[1] + red[2] + red[3] + 1e-7f);
}

// ---------------- scatter (last-write-wins) ----------------
__global__ void scatter_kernel(const float* __restrict__ u,
                               const float* __restrict__ all_span,
                               const int* __restrict__ prune,
                               const int* __restrict__ span_len,
                               float* __restrict__ out_all)
{
    int bk = blockIdx.x;
    int b = bk / K_, k = bk % K_;
    int idx = prune[bk];
    bool last = (k == K_ - 1) || (prune[bk + 1] != idx);
    if (!last) return;
    bool valid = k < span_len[b];
    const float* src = valid ? (u + (long)bk * D_)
                             : (all_span + ((long)b * N_ + idx) * D_);
    float* dst = out_all + ((long)b * N_ + idx) * D_;
    int t = threadIdx.x;
    float4 v = *(const float4*)(src + t * 4);
    *(float4*)(dst + t * 4) = v;
}

// ---------------- host orchestration ----------------
extern "C" void kernel_launch(void* const* d_in, const int* in_sizes, int n_in,
                              void* d_out, int out_size)
{
    const float* span_vecs  = (const float*)d_in[0];
    const float* all_span   = (const float*)d_in[1];
    const int*   span_begin = (const int*)  d_in[2];
    const int*   span_end   = (const int*)  d_in[3];
    const float* mask       = (const float*)d_in[4];
    const int*   prune      = (const int*)  d_in[5];
    const int*   span_len   = (const int*)  d_in[6];
    const float* Wl  = (const float*)d_in[8];
    const float* bl  = (const float*)d_in[9];
    const float* Wr  = (const float*)d_in[10];
    const float* br  = (const float*)d_in[11];
    const float* de  = (const float*)d_in[12];
    const float* Wd  = (const float*)d_in[13];
    const float* bd  = (const float*)d_in[14];
    const float* Wo  = (const float*)d_in[15];
    const float* bo  = (const float*)d_in[16];
    const float* Wff1= (const float*)d_in[17];
    const float* Wff2= (const float*)d_in[18];
    const float* Wg  = (const float*)d_in[19];
    const float* bg  = (const float*)d_in[20];

    float *u, *u2, *ut, *ut2, *lr, *wlr, *blr, *dp, *probsAll, *invAll, *c, *tmp, *ctxt;
    float *wff1t, *wff2t, *wgt;
    cudaGetSymbolAddress((void**)&u,        g_u);
    cudaGetSymbolAddress((void**)&u2,       g_u2);
    cudaGetSymbolAddress((void**)&ut,       g_ut);
    cudaGetSymbolAddress((void**)&ut2,      g_ut2);
    cudaGetSymbolAddress((void**)&lr,       g_lr);
    cudaGetSymbolAddress((void**)&wlr,      g_wlr);
    cudaGetSymbolAddress((void**)&blr,      g_blr);
    cudaGetSymbolAddress((void**)&dp,       g_dp);
    cudaGetSymbolAddress((void**)&probsAll, g_probs);
    cudaGetSymbolAddress((void**)&invAll,   g_inv);
    cudaGetSymbolAddress((void**)&c,        g_c);
    cudaGetSymbolAddress((void**)&tmp,      g_tmp);
    cudaGetSymbolAddress((void**)&ctxt,     g_ctxt);
    cudaGetSymbolAddress((void**)&wff1t,    g_wff1t);
    cudaGetSymbolAddress((void**)&wff2t,    g_wff2t);
    cudaGetSymbolAddress((void**)&wgt,      g_wgt);

    float* out_all = (float*)d_out;
    float* out_u   = out_all + (size_t)B_ * N_ * D_;
    float* out_sc  = out_u   + (size_t)B_ * K_ * D_;

    const int M = B_ * K_;

    const int smem64 = 3 * (64 * ASTRIDE + 32 * BSTRIDE) * 4;
    const int smem32 = 3 * (32 * ASTRIDE + 32 * BSTRIDE) * 4;
    const int smemSc = SCOR_SMEM_WORDS * 4;
    cudaFuncSetAttribute(mma_gemm<64>, cudaFuncAttributeMaxDynamicSharedMemorySize, smem64);
    cudaFuncSetAttribute(scorer_tc, cudaFuncAttributeMaxDynamicSharedMemorySize, smemSc);

    convert_kernel<<<148, 256>>>(Wff1, Wff2, Wg, span_vecs, wff1t, wff2t, wgt, u, ut);
    init_kernel<<<128, 256>>>(de, Wd, bd, Wl, bl, Wr, br, dp, wlr, blr);

    float *ucur = u,  *unext = u2;
    float *utcur = ut, *utnext = ut2;

    mma_gemm<32><<<dim3(6, 24, 1), 64, smem32>>>(utcur, utcur, utcur, wlr, blr, nullptr, nullptr, nullptr,
                                                 lr, nullptr, M, LRWP_, D_, D_, LRWP_, 0, 0, 0, 0, 0, 0, 0);
    scorer_tc<<<dim3(K_, B_), 256, smemSc>>>(lr, dp, Wo, bo, span_begin, span_end, out_sc, 1);

    for (int it = 0; it < 2; it++) {
        probs_kernel<<<dim3(K_, B_), 128>>>(out_sc, mask, probsAll, invAll);
        invsum_kernel<<<B_ * K_, 128>>>(probsAll, invAll);

        mma_gemm<64><<<dim3(16, 6, 4), 64, smem64>>>(probsAll, probsAll, probsAll, utcur, nullptr, invAll,
                                                     nullptr, nullptr, c, nullptr,
                                                     K_, D_, K_, K_, D_,
                                                     (long)K_*K_, (long)K_*D_, 1, (long)K_*D_, K_, 0, 1);

        mma_gemm<64><<<dim3(16, 12, 1), 64, smem64>>>(utcur, c, c + SZ_U, wff1t, nullptr, nullptr,
                                                      nullptr, nullptr, tmp, nullptr,
                                                      M, D_, 3 * D_, D_, D_, 0, 0, 0, 0, 0, 1, 1);
        mma_gemm<64><<<dim3(16, 12, 1), 64, smem64>>>(tmp, tmp, tmp, wff2t, nullptr, nullptr,
                                                      nullptr, nullptr, ctxt, nullptr,
                                                      M, D_, D_, D_, D_, 0, 0, 0, 0, 0, 0, 1);
        mma_gemm<64><<<dim3(16, 12, 1), 64, smem64>>>(utcur, ctxt, ctxt, wgt, bg, nullptr,
                                                      ucur, ctxt, unext, utnext,
                                                      M, D_, 2 * D_, D_, D_, 0, 0, 0, 0, 0, 3, 0);
        float* s1 = ucur; ucur = unext; unext = s1;
        float* s2 = utcur; utcur = utnext; utnext = s2;

        mma_gemm<32><<<dim3(6, 24, 1), 64, smem32>>>(utcur, utcur, utcur, wlr, blr, nullptr, nullptr, nullptr,
                                                     lr, nullptr, M, LRWP_, D_, D_, LRWP_, 0, 0, 0, 0, 0, 0, 0);
        scorer_tc<<<dim3(K_, B_), 256, smemSc>>>(lr, dp, Wo, bo, span_begin, span_end, out_sc, 0);
    }

    cudaMemcpyAsync(out_all, all_span, sizeof(float) * (size_t)B_ * N_ * D_, cudaMemcpyDeviceToDevice);
    scatter_kernel<<<B_ * K_, 256>>>(ucur, all_span, prune, span_len, out_all);
    cudaMemcpyAsync(out_u, ucur, sizeof(float) * SZ_U, cudaMemcpyDeviceToDevice);
}

// round 10
// speedup vs baseline: 1.1139x; 1.1139x over previous
#include <cuda_runtime.h>
#include <math.h>

// ---------------- problem constants ----------------
#define B_    2
#define K_    384
#define N_    4096
#define D_    1024
#define H_    150
#define HP_   152
#define LRWP_ 384
#define L_    12
#define NB_   10
#define DE_   20

#define SZ_U   (B_*K_*D_)
#define SZ_P   (B_*K_*K_)
#define SZ_S   (B_*K_)

// ---------------- device scratch ----------------
__device__ float g_u[SZ_U];
__device__ float g_u2[SZ_U];
__device__ float g_ut[SZ_U];
__device__ float g_ut2[SZ_U];
__device__ float g_lr[B_*K_*LRWP_];
__device__ float g_wlr[D_*LRWP_];
__device__ float g_blr[LRWP_];
__device__ float g_dp[NB_*HP_];
__device__ float g_probs[2*SZ_P];
__device__ float g_inv[2*SZ_S];
__device__ float g_c[2*SZ_U];
__device__ float g_tmp[SZ_U];
__device__ float g_ctxt[SZ_U];
__device__ float g_wff1t[3*D_*D_];
__device__ float g_wff2t[D_*D_];
__device__ float g_wgt[2*D_*D_];

__device__ __forceinline__ unsigned f2t(float x) {
    unsigned r;
    asm("cvt.rna.tf32.f32 %0, %1;" : "=r"(r) : "f"(x));
    return r;
}
__device__ __forceinline__ float rna(float x) { return __uint_as_float(f2t(x)); }

__device__ __forceinline__ void cpa16(void* s, const void* g) {
    unsigned sa = (unsigned)__cvta_generic_to_shared(s);
    asm volatile("cp.async.cg.shared.global [%0], [%1], 16;" :: "r"(sa), "l"(g));
}
__device__ __forceinline__ void cp_commit() { asm volatile("cp.async.commit_group;"); }
template<int Nw>
__device__ __forceinline__ void cp_wait() { asm volatile("cp.async.wait_group %0;" :: "n"(Nw)); }

// ---------------- weight/input tf32 conversion ----------------
__global__ void convert_kernel(const float* __restrict__ Wff1,
                               const float* __restrict__ Wff2,
                               const float* __restrict__ Wg,
                               const float* __restrict__ span_vecs,
                               float* __restrict__ wff1t,
                               float* __restrict__ wff2t,
                               float* __restrict__ wgt,
                               float* __restrict__ u,
                               float* __restrict__ ut)
{
    int tid = blockIdx.x * blockDim.x + threadIdx.x;
    int nthr = gridDim.x * blockDim.x;
    for (int i = tid; i < 3*D_*D_; i += nthr) wff1t[i] = rna(Wff1[i]);
    for (int i = tid; i < D_*D_;   i += nthr) wff2t[i] = rna(Wff2[i]);
    for (int i = tid; i < 2*D_*D_; i += nthr) wgt[i]   = rna(Wg[i]);
    for (int i = tid; i < SZ_U; i += nthr) {
        float v = span_vecs[i];
        u[i] = v;
        ut[i] = rna(v);
    }
}

// ---------------- init: dp table + W_lr / b_lr concat ----------------
__global__ void init_kernel(const float* __restrict__ dist_emb,
                            const float* __restrict__ Wd,
                            const float* __restrict__ bd,
                            const float* __restrict__ Wl,
                            const float* __restrict__ bl,
                            const float* __restrict__ Wr,
                            const float* __restrict__ br,
                            float* __restrict__ dp,
                            float* __restrict__ wlr,
                            float* __restrict__ blr)
{
    int tid = blockIdx.x * blockDim.x + threadIdx.x;
    int nthr = gridDim.x * blockDim.x;
    for (int idx = tid; idx < NB_*HP_; idx += nthr) {
        int n = idx / HP_, h = idx % HP_;
        float v = 0.f;
        if (h < H_) {
            v = bd[h];
            #pragma unroll
            for (int t = 0; t < DE_; t++)
                v += dist_emb[n * DE_ + t] * Wd[t * H_ + h];
        }
        dp[idx] = v;
    }
    for (int idx = tid; idx < D_*LRWP_; idx += nthr) {
        int k = idx / LRWP_, c = idx % LRWP_;
        float v = 0.f;
        if (c < H_) v = Wl[k * H_ + c];
        else if (c >= HP_ && c < HP_ + H_) v = Wr[k * H_ + (c - HP_)];
        wlr[idx] = rna(v);
    }
    for (int c = tid; c < LRWP_; c += nthr) {
        float v = 0.f;
        if (c < H_) v = bl[c];
        else if (c >= HP_ && c < HP_ + H_) v = br[c - HP_];
        blr[c] = v;
    }
}

// ---------------- tf32 GEMM (R8 config): 128 thr, 4 warps (2x2), 3-stage cp.async ----------------
#define ASTRIDE 36
#define BSTRIDE 72
template<int BM>
__global__ void __launch_bounds__(128, 2)
mma_gemm(const float* __restrict__ a0,
         const float* __restrict__ a1,
         const float* __restrict__ a2,
         const float* __restrict__ W,
         const float* __restrict__ bias,
         const float* __restrict__ rowscale,
         const float* __restrict__ e1,
         const float* __restrict__ e2,
         float* __restrict__ Cout,
         float* __restrict__ Ct,
         int M, int N, int K, int lda, int ldc,
         long sA, long sW, int bzmask, long sC, int sRS,
         int act, int roundOut)
{
    constexpr int MT = BM / 32;
    constexpr int ACH = (BM == 64) ? 4 : 2;
    constexpr int ASZ = BM * ASTRIDE;
    constexpr int BSZ = 32 * BSTRIDE;
    extern __shared__ unsigned dsm[];
    unsigned* Abase = dsm;
    unsigned* Bbase = dsm + 3 * ASZ;

    int z = blockIdx.z;
    a0 += (long)z * sA;
    W  += (long)(z & bzmask) * sW;
    Cout += (long)z * sC;
    if (rowscale) rowscale += (long)z * sRS;

    int tid = threadIdx.x;
    int warp = tid >> 5, lane = tid & 31;
    int m0 = blockIdx.y * BM, n0 = blockIdx.x * 64;
    int wm = (warp >> 1) * (BM / 2), wn = (warp & 1) * 32;

    auto issue = [&](int k0, int stage) {
        unsigned* As = Abase + stage * ASZ;
        unsigned* Bs = Bbase + stage * BSZ;
        int seg = k0 >> 10, col = k0 & 1023;
        const float* ap = (seg == 0) ? a0 : (seg == 1) ? a1 : a2;
        #pragma unroll
        for (int i = 0; i < ACH; i++) {
            int id = tid + i * 128;
            int row = id >> 3, c16 = (id & 7) * 4;
            cpa16(As + row * ASTRIDE + c16, ap + (long)(m0 + row) * lda + col + c16);
        }
        #pragma unroll
        for (int i = 0; i < 4; i++) {
            int id = tid + i * 128;
            int kr = id >> 4, c16 = (id & 15) * 4;
            cpa16(Bs + kr * BSTRIDE + c16, W + (long)(k0 + kr) * N + n0 + c16);
        }
        cp_commit();
    };

    int nt = K >> 5;
    issue(0, 0);
    issue(32, 1);

    float acc[MT][4][4];
    #pragma unroll
    for (int i = 0; i < MT; i++)
        #pragma unroll
        for (int j = 0; j < 4; j++)
            #pragma unroll
            for (int q = 0; q < 4; q++) acc[i][j][q] = 0.f;

    int stage = 0;
    for (int t = 0; t < nt; t++) {
        if (t == nt - 1) cp_wait<0>(); else cp_wait<1>();
        __syncthreads();
        if (t + 2 < nt) issue((t + 2) << 5, (stage + 2) % 3);

        unsigned* As = Abase + stage * ASZ;
        unsigned* Bs = Bbase + stage * BSZ;

        #pragma unroll
        for (int kx = 0; kx < 4; kx++) {
            unsigned a[MT][4];
            #pragma unroll
            for (int mt = 0; mt < MT; mt++) {
                int r_ = wm + mt * 16 + (lane >> 2);
                int c_ = kx * 8 + (lane & 3);
                a[mt][0] = As[r_ * ASTRIDE + c_];
                a[mt][1] = As[(r_ + 8) * ASTRIDE + c_];
                a[mt][2] = As[r_ * ASTRIDE + c_ + 4];
                a[mt][3] = As[(r_ + 8) * ASTRIDE + c_ + 4];
            }
            #pragma unroll
            for (int ct = 0; ct < 4; ct++) {
                unsigned b0 = Bs[(kx*8 + (lane & 3)) * BSTRIDE + wn + ct*8 + (lane >> 2)];
                unsigned b1 = Bs[(kx*8 + (lane & 3) + 4) * BSTRIDE + wn + ct*8 + (lane >> 2)];
                #pragma unroll
                for (int mt = 0; mt < MT; mt++) {
                    asm volatile(
                        "mma.sync.aligned.m16n8k8.row.col.f32.tf32.tf32.f32 "
                        "{%0,%1,%2,%3}, {%4,%5,%6,%7}, {%8,%9}, {%0,%1,%2,%3};"
                        : "+f"(acc[mt][ct][0]), "+f"(acc[mt][ct][1]),
                          "+f"(acc[mt][ct][2]), "+f"(acc[mt][ct][3])
                        : "r"(a[mt][0]), "r"(a[mt][1]), "r"(a[mt][2]), "r"(a[mt][3]),
                          "r"(b0), "r"(b1));
                }
            }
        }
        stage = (stage + 1) % 3;
    }

    #pragma unroll
    for (int mt = 0; mt < MT; mt++) {
        #pragma unroll
        for (int rh = 0; rh < 2; rh++) {
            int gm = m0 + wm + mt * 16 + (lane >> 2) + rh * 8;
            float rs = rowscale ? rowscale[gm] : 1.f;
            #pragma unroll
            for (int ct = 0; ct < 4; ct++) {
                int gn = n0 + wn + ct * 8 + (lane & 3) * 2;
                float v0 = acc[mt][ct][rh * 2 + 0];
                float v1 = acc[mt][ct][rh * 2 + 1];
                if (bias) { v0 += bias[gn]; v1 += bias[gn + 1]; }
                v0 *= rs; v1 *= rs;
                long off = (long)gm * ldc + gn;
                if (act == 1) { v0 = tanhf(v0); v1 = tanhf(v1); }
                else if (act == 2) {
                    v0 = 1.f / (1.f + expf(-v0));
                    v1 = 1.f / (1.f + expf(-v1));
                }
                else if (act == 3) {
                    float g0 = 1.f / (1.f + expf(-v0));
                    float g1 = 1.f / (1.f + expf(-v1));
                    v0 = g0 * e1[off]     + (1.f - g0) * e2[off];
                    v1 = g1 * e1[off + 1] + (1.f - g1) * e2[off + 1];
                }
                if (roundOut) { v0 = rna(v0); v1 = rna(v1); }
                *(float2*)(Cout + off) = make_float2(v0, v1);
                if (Ct) *(float2*)(Ct + off) = make_float2(rna(v0), rna(v1));
            }
        }
    }
}

// ---------------- TC scorer v4 (from R8/R9) ----------------
#define SCOR_HSTRIDE 156
#define SCOR_SMEM_WORDS (NB_*HP_ + 2*(2*19*32) + K_ + 16 + 8*16*SCOR_HSTRIDE)
__global__ void __launch_bounds__(256)
scorer_tc(const float* __restrict__ lr,
          const float* __restrict__ dp,
          const float* __restrict__ Wo,
          const float* __restrict__ bo,
          const int* __restrict__ span_begin,
          const int* __restrict__ span_end,
          float* __restrict__ scores,
          int first)
{
    extern __shared__ float sm[];
    float* s_t  = sm;
    uint2* s_w2 = (uint2*)(sm + NB_*HP_);
    int*   s_bk = (int*)(s_w2 + 2*19*32);
    float* s_bo = (float*)(s_bk + K_);
    float* s_h  = s_bo + 16;

    int i = blockIdx.x, b = blockIdx.y;
    int tid = threadIdx.x;
    int warp = tid >> 5, lane = tid & 31;

    const float* lrow = lr + (long)(b * K_ + i) * LRWP_;
    for (int x = tid; x < NB_ * HP_; x += 256)
        s_t[x] = rna(lrow[x % HP_] + dp[x]);

    for (int x = tid; x < 2 * 19 * 32; x += 256) {
        int ln = x & 31, kt = (x >> 5) % 19, nt = x / (19 * 32);
        int k0 = kt * 8 + (ln & 3), k1 = k0 + 4;
        int n  = nt * 8 + (ln >> 2);
        uint2 v;
        v.x = (k0 < H_ && n < L_) ? f2t(Wo[k0 * L_ + n]) : 0u;
        v.y = (k1 < H_ && n < L_) ? f2t(Wo[k1 * L_ + n]) : 0u;
        s_w2[x] = v;
    }

    int endi = span_end[b * K_ + i];
    for (int j = tid; j < K_; j += 256) {
        int d = span_begin[b * K_ + j] - endi;
        int da = d < 0 ? -d : d;
        int bk;
        if (da <= 4) bk = da;
        else {
            int lg = 31 - __clz(da) + 3;
            bk = lg < (NB_ - 1) ? lg : (NB_ - 1);
        }
        s_bk[j] = bk;
    }
    if (tid < 16) s_bo[tid] = (tid < L_) ? bo[tid] : 0.f;
    __syncthreads();

    float* hbase = s_h + warp * (16 * SCOR_HSTRIDE);
    const float* rbase = lr + (long)b * K_ * LRWP_ + HP_;
    int row = lane >> 1, half = lane & 1;
    int ar = lane >> 2, ac = lane & 3;
    long srow = (long)(b * K_ + i) * K_;
    int gc0 = (lane & 3) * 2;
    int gc1 = 8 + gc0;
    bool nt1ok = gc1 < L_;

    #pragma unroll
    for (int s = 0; s < 3; s++) {
        int j0 = (s * 8 + warp) * 16;

        long o0 = (srow + j0 + ar) * L_ + gc0;
        float2 q00, q01, q10, q11;
        if (!first) {
            q00 = *(float2*)(scores + o0);
            q01 = *(float2*)(scores + o0 + 8 * L_);
            if (nt1ok) {
                q10 = *(float2*)(scores + o0 + 8);
                q11 = *(float2*)(scores + o0 + 8 * L_ + 8);
            }
        }

        {
            int j = j0 + row;
            const float* rr = rbase + (long)j * LRWP_ + half * 76;
            const float* tt = s_t + s_bk[j] * HP_ + half * 76;
            float* hh = hbase + row * SCOR_HSTRIDE + half * 76;
            #pragma unroll
            for (int x = 0; x < 19; x++) {
                float4 rv = *(const float4*)(rr + x * 4);
                float4 tv = *(const float4*)(tt + x * 4);
                float4 hv;
                hv.x = rna(fmaxf(rv.x + tv.x, 0.f));
                hv.y = rna(fmaxf(rv.y + tv.y, 0.f));
                hv.z = rna(fmaxf(rv.z + tv.z, 0.f));
                hv.w = rna(fmaxf(rv.w + tv.w, 0.f));
                *(float4*)(hh + x * 4) = hv;
            }
        }
        __syncwarp();

        float acc0[2][4] = {{0.f,0.f,0.f,0.f},{0.f,0.f,0.f,0.f}};
        float acc1[2][4] = {{0.f,0.f,0.f,0.f},{0.f,0.f,0.f,0.f}};
        #pragma unroll
        for (int kt = 0; kt < 19; kt++) {
            int p = kt & 1;
            unsigned a0 = __float_as_uint(hbase[ar * SCOR_HSTRIDE + kt * 8 + ac]);
            unsigned a1 = __float_as_uint(hbase[(ar + 8) * SCOR_HSTRIDE + kt * 8 + ac]);
            unsigned a2 = __float_as_uint(hbase[ar * SCOR_HSTRIDE + kt * 8 + ac + 4]);
            unsigned a3 = __float_as_uint(hbase[(ar + 8) * SCOR_HSTRIDE + kt * 8 + ac + 4]);
            uint2 w0 = s_w2[kt * 32 + lane];
            uint2 w1 = s_w2[(19 + kt) * 32 + lane];
            asm volatile(
                "mma.sync.aligned.m16n8k8.row.col.f32.tf32.tf32.f32 "
                "{%0,%1,%2,%3}, {%4,%5,%6,%7}, {%8,%9}, {%0,%1,%2,%3};"
                : "+f"(acc0[p][0]), "+f"(acc0[p][1]), "+f"(acc0[p][2]), "+f"(acc0[p][3])
                : "r"(a0), "r"(a1), "r"(a2), "r"(a3), "r"(w0.x), "r"(w0.y));
            asm volatile(
                "mma.sync.aligned.m16n8k8.row.col.f32.tf32.tf32.f32 "
                "{%0,%1,%2,%3}, {%4,%5,%6,%7}, {%8,%9}, {%0,%1,%2,%3};"
                : "+f"(acc1[p][0]), "+f"(acc1[p][1]), "+f"(acc1[p][2]), "+f"(acc1[p][3])
                : "r"(a0), "r"(a1), "r"(a2), "r"(a3), "r"(w1.x), "r"(w1.y));
        }

        {
            float v0 = acc0[0][0] + acc0[1][0] + s_bo[gc0];
            float v1 = acc0[0][1] + acc0[1][1] + s_bo[gc0 + 1];
            float v2 = acc0[0][2] + acc0[1][2] + s_bo[gc0];
            float v3 = acc0[0][3] + acc0[1][3] + s_bo[gc0 + 1];
            if (!first) { v0 += q00.x; v1 += q00.y; v2 += q01.x; v3 += q01.y; }
            *(float2*)(scores + o0)          = make_float2(v0, v1);
            *(float2*)(scores + o0 + 8 * L_) = make_float2(v2, v3);
        }
        if (nt1ok) {
            float v0 = acc1[0][0] + acc1[1][0] + s_bo[gc1];
            float v1 = acc1[0][1] + acc1[1][1] + s_bo[gc1 + 1];
            float v2 = acc1[0][2] + acc1[1][2] + s_bo[gc1];
            float v3 = acc1[0][3] + acc1[1][3] + s_bo[gc1 + 1];
            if (!first) { v0 += q10.x; v1 += q10.y; v2 += q11.x; v3 += q11.y; }
            *(float2*)(scores + o0 + 8)          = make_float2(v0, v1);
            *(float2*)(scores + o0 + 8 * L_ + 8) = make_float2(v2, v3);
        }
        __syncwarp();
    }
}

// ---------------- probs + row-sums fused ----------------
__global__ void probs_kernel(const float* __restrict__ scores,
                             const float* __restrict__ mask,
                             float* __restrict__ probsAll,
                             float* __restrict__ invAll)
{
    int i = blockIdx.x, b = blockIdx.y;
    float ssum = 0.f;
    for (int j = threadIdx.x; j < K_; j += blockDim.x) {
        const float* s = scores + (((long)(b * K_ + i)) * K_ + j) * L_;
        float m = s[0];
        #pragma unroll
        for (int c = 1; c < L_; c++) m = fmaxf(m, s[c]);
        float p = rna((1.f / (1.f + expf(-m))) * mask[((long)(b * K_ + i)) * K_ + j]);
        probsAll[((long)(b * K_ + i)) * K_ + j] = p;
        probsAll[(long)SZ_P + ((long)(b * K_ + j)) * K_ + i] = p;
        ssum += p;
    }
    __shared__ float red[4];
    #pragma unroll
    for (int o = 16; o > 0; o >>= 1) ssum += __shfl_down_sync(0xffffffffu, ssum, o);
    int wid = threadIdx.x >> 5;
    if ((threadIdx.x & 31) == 0) red[wid] = ssum;
    __syncthreads();
    if (threadIdx.x == 0)
        invAll[b * K_ + i] = 1.f / (red[0] + red[1] + red[2] + red[3] + 1e-7f);
}

// ---------------- inverse column sums (probsT rows) ----------------
__global__ void invsum_kernel(const float* __restrict__ probsAll,
                              float* __restrict__ invAll)
{
    int row = blockIdx.x;
    const float* src = probsAll + (long)SZ_P + (long)row * K_;
    float s = 0.f;
    for (int j = threadIdx.x; j < K_; j += blockDim.x) s += src[j];
    __shared__ float red[4];
    #pragma unroll
    for (int o = 16; o > 0; o >>= 1) s += __shfl_down_sync(0xffffffffu, s, o);
    int wid = threadIdx.x >> 5;
    if ((threadIdx.x & 31) == 0) red[wid] = s;
    __syncthreads();
    if (threadIdx.x == 0)
        invAll[SZ_S + row] = 1.f / (red[0] + red[1] + red[2] + red[3] + 1e-7f);
}

// ---------------- scatter (last-write-wins) ----------------
__global__ void scatter_kernel(const float* __restrict__ u,
                               const float* __restrict__ all_span,
                               const int* __restrict__ prune,
                               const int* __restrict__ span_len,
                               float* __restrict__ out_all)
{
    int bk = blockIdx.x;
    int b = bk / K_, k = bk % K_;
    int idx = prune[bk];
    bool last = (k == K_ - 1) || (prune[bk + 1] != idx);
    if (!last) return;
    bool valid = k < span_len[b];
    const float* src = valid ? (u + (long)bk * D_)
                             : (all_span + ((long)b * N_ + idx) * D_);
    float* dst = out_all + ((long)b * N_ + idx) * D_;
    int t = threadIdx.x;
    float4 v = *(const float4*)(src + t * 4);
    *(float4*)(dst + t * 4) = v;
}

// ---------------- host orchestration ----------------
extern "C" void kernel_launch(void* const* d_in, const int* in_sizes, int n_in,
                              void* d_out, int out_size)
{
    const float* span_vecs  = (const float*)d_in[0];
    const float* all_span   = (const float*)d_in[1];
    const int*   span_begin = (const int*)  d_in[2];
    const int*   span_end   = (const int*)  d_in[3];
    const float* mask       = (const float*)d_in[4];
    const int*   prune      = (const int*)  d_in[5];
    const int*   span_len   = (const int*)  d_in[6];
    const float* Wl  = (const float*)d_in[8];
    const float* bl  = (const float*)d_in[9];
    const float* Wr  = (const float*)d_in[10];
    const float* br  = (const float*)d_in[11];
    const float* de  = (const float*)d_in[12];
    const float* Wd  = (const float*)d_in[13];
    const float* bd  = (const float*)d_in[14];
    const float* Wo  = (const float*)d_in[15];
    const float* bo  = (const float*)d_in[16];
    const float* Wff1= (const float*)d_in[17];
    const float* Wff2= (const float*)d_in[18];
    const float* Wg  = (const float*)d_in[19];
    const float* bg  = (const float*)d_in[20];

    float *u, *u2, *ut, *ut2, *lr, *wlr, *blr, *dp, *probsAll, *invAll, *c, *tmp, *ctxt;
    float *wff1t, *wff2t, *wgt;
    cudaGetSymbolAddress((void**)&u,        g_u);
    cudaGetSymbolAddress((void**)&u2,       g_u2);
    cudaGetSymbolAddress((void**)&ut,       g_ut);
    cudaGetSymbolAddress((void**)&ut2,      g_ut2);
    cudaGetSymbolAddress((void**)&lr,       g_lr);
    cudaGetSymbolAddress((void**)&wlr,      g_wlr);
    cudaGetSymbolAddress((void**)&blr,      g_blr);
    cudaGetSymbolAddress((void**)&dp,       g_dp);
    cudaGetSymbolAddress((void**)&probsAll, g_probs);
    cudaGetSymbolAddress((void**)&invAll,   g_inv);
    cudaGetSymbolAddress((void**)&c,        g_c);
    cudaGetSymbolAddress((void**)&tmp,      g_tmp);
    cudaGetSymbolAddress((void**)&ctxt,     g_ctxt);
    cudaGetSymbolAddress((void**)&wff1t,    g_wff1t);
    cudaGetSymbolAddress((void**)&wff2t,    g_wff2t);
    cudaGetSymbolAddress((void**)&wgt,      g_wgt);

    float* out_all = (float*)d_out;
    float* out_u   = out_all + (size_t)B_ * N_ * D_;
    float* out_sc  = out_u   + (size_t)B_ * K_ * D_;

    const int M = B_ * K_;

    const int smem32 = 3 * (32 * ASTRIDE + 32 * BSTRIDE) * 4;  // 41472
    const int smemSc = SCOR_SMEM_WORDS * 4;
    cudaFuncSetAttribute(mma_gemm<32>, cudaFuncAttributeMaxDynamicSharedMemorySize, smem32);
    cudaFuncSetAttribute(scorer_tc, cudaFuncAttributeMaxDynamicSharedMemorySize, smemSc);

    convert_kernel<<<148, 256>>>(Wff1, Wff2, Wg, span_vecs, wff1t, wff2t, wgt, u, ut);
    init_kernel<<<128, 256>>>(de, Wd, bd, Wl, bl, Wr, br, dp, wlr, blr);

    float *ucur = u,  *unext = u2;
    float *utcur = ut, *utnext = ut2;

    // initial l|r projection (BM=32, grid 6x24 = 144 CTAs) + scorer
    mma_gemm<32><<<dim3(6, 24, 1), 128, smem32>>>(utcur, utcur, utcur, wlr, blr, nullptr, nullptr, nullptr,
                                                  lr, nullptr, M, LRWP_, D_, D_, LRWP_, 0, 0, 0, 0, 0, 0, 0);
    scorer_tc<<<dim3(K_, B_), 256, smemSc>>>(lr, dp, Wo, bo, span_begin, span_end, out_sc, 1);

    for (int it = 0; it < 2; it++) {
        probs_kernel<<<dim3(K_, B_), 128>>>(out_sc, mask, probsAll, invAll);
        invsum_kernel<<<B_ * K_, 128>>>(probsAll, invAll);

        // c[z] = (probsAll[z] @ ut[z&1]) * invAll[z]  (BM=32, grid 16x12x4 = 768 CTAs)
        mma_gemm<32><<<dim3(16, 12, 4), 128, smem32>>>(probsAll, probsAll, probsAll, utcur, nullptr, invAll,
                                                       nullptr, nullptr, c, nullptr,
                                                       K_, D_, K_, K_, D_,
                                                       (long)K_*K_, (long)K_*D_, 1, (long)K_*D_, K_, 0, 1);

        // tmp = tanh([ut|c1|c2] @ Wff1)   (BM=32, grid 16x24 = 384 CTAs)
        mma_gemm<32><<<dim3(16, 24, 1), 128, smem32>>>(utcur, c, c + SZ_U, wff1t, nullptr, nullptr,
                                                       nullptr, nullptr, tmp, nullptr,
                                                       M, D_, 3 * D_, D_, D_, 0, 0, 0, 0, 0, 1, 1);
        // ctxt = tmp @ Wff2
        mma_gemm<32><<<dim3(16, 24, 1), 128, smem32>>>(tmp, tmp, tmp, wff2t, nullptr, nullptr,
                                                       nullptr, nullptr, ctxt, nullptr,
                                                       M, D_, D_, D_, D_, 0, 0, 0, 0, 0, 0, 1);
        // unext = g*u + (1-g)*ctxt (fp32), utnext = rna(unext)
        mma_gemm<32><<<dim3(16, 24, 1), 128, smem32>>>(utcur, ctxt, ctxt, wgt, bg, nullptr,
                                                       ucur, ctxt, unext, utnext,
                                                       M, D_, 2 * D_, D_, D_, 0, 0, 0, 0, 0, 3, 0);
        float* s1 = ucur; ucur = unext; unext = s1;
        float* s2 = utcur; utcur = utnext; utnext = s2;

        // re-project + scorer (residual accumulate)
        mma_gemm<32><<<dim3(6, 24, 1), 128, smem32>>>(utcur, utcur, utcur, wlr, blr, nullptr, nullptr, nullptr,
                                                      lr, nullptr, M, LRWP_, D_, D_, LRWP_, 0, 0, 0, 0, 0, 0, 0);
        scorer_tc<<<dim3(K_, B_), 256, smemSc>>>(lr, dp, Wo, bo, span_begin, span_end, out_sc, 0);
    }

    cudaMemcpyAsync(out_all, all_span, sizeof(float) * (size_t)B_ * N_ * D_, cudaMemcpyDeviceToDevice);
    scatter_kernel<<<B_ * K_, 256>>>(ucur, all_span, prune, span_len, out_all);
    cudaMemcpyAsync(out_u, ucur, sizeof(float) * SZ_U, cudaMemcpyDeviceToDevice);
}

// round 13
// speedup vs baseline: 1.2047x; 1.0815x over previous
#include <cuda_runtime.h>
#include <math.h>
#include <stdint.h>

// ---------------- problem constants ----------------
#define B_    2
#define K_    384
#define N_    4096
#define D_    1024
#define H_    150
#define HP_   152
#define LRWP_ 384
#define L_    12
#define NB_   10
#define DE_   20

#define SZ_U   (B_*K_*D_)
#define SZ_P   (B_*K_*K_)
#define SZ_S   (B_*K_)

// ---------------- device scratch ----------------
__device__ float g_u[SZ_U];
__device__ float g_u2[SZ_U];
__device__ float g_ut[SZ_U];
__device__ float g_ut2[SZ_U];
__device__ float g_lr[B_*K_*LRWP_];
__device__ float g_wlr[D_*LRWP_];
__device__ float g_blr[LRWP_];
__device__ float g_dp[NB_*HP_];
__device__ float g_probs[2*SZ_P];
__device__ float g_inv[2*SZ_S];
__device__ float g_c[2*SZ_U];
__device__ float g_tmp[SZ_U];
__device__ float g_ctxt[SZ_U];
__device__ float g_wff1t[3*D_*D_];
__device__ float g_wff2t[D_*D_];
__device__ float g_wgt[2*D_*D_];

__device__ __forceinline__ unsigned f2t(float x) {
    unsigned r;
    asm("cvt.rna.tf32.f32 %0, %1;" : "=r"(r) : "f"(x));
    return r;
}
__device__ __forceinline__ float rna(float x) { return __uint_as_float(f2t(x)); }

__device__ __forceinline__ void cpa16(void* s, const void* g) {
    unsigned sa = (unsigned)__cvta_generic_to_shared(s);
    asm volatile("cp.async.cg.shared.global [%0], [%1], 16;" :: "r"(sa), "l"(g));
}
__device__ __forceinline__ void cp_commit() { asm volatile("cp.async.commit_group;"); }
template<int Nw>
__device__ __forceinline__ void cp_wait() { asm volatile("cp.async.wait_group %0;" :: "n"(Nw)); }

// ---------------- weight/input tf32 conversion ----------------
__global__ void convert_kernel(const float* __restrict__ Wff1,
                               const float* __restrict__ Wff2,
                               const float* __restrict__ Wg,
                               const float* __restrict__ span_vecs,
                               float* __restrict__ wff1t,
                               float* __restrict__ wff2t,
                               float* __restrict__ wgt,
                               float* __restrict__ u,
                               float* __restrict__ ut)
{
    int tid = blockIdx.x * blockDim.x + threadIdx.x;
    int nthr = gridDim.x * blockDim.x;
    for (int i = tid; i < 3*D_*D_; i += nthr) wff1t[i] = rna(Wff1[i]);
    for (int i = tid; i < D_*D_;   i += nthr) wff2t[i] = rna(Wff2[i]);
    for (int i = tid; i < 2*D_*D_; i += nthr) wgt[i]   = rna(Wg[i]);
    for (int i = tid; i < SZ_U; i += nthr) {
        float v = span_vecs[i];
        u[i] = v;
        ut[i] = rna(v);
    }
}

// ---------------- init: dp table + W_lr / b_lr concat ----------------
__global__ void init_kernel(const float* __restrict__ dist_emb,
                            const float* __restrict__ Wd,
                            const float* __restrict__ bd,
                            const float* __restrict__ Wl,
                            const float* __restrict__ bl,
                            const float* __restrict__ Wr,
                            const float* __restrict__ br,
                            float* __restrict__ dp,
                            float* __restrict__ wlr,
                            float* __restrict__ blr)
{
    int tid = blockIdx.x * blockDim.x + threadIdx.x;
    int nthr = gridDim.x * blockDim.x;
    for (int idx = tid; idx < NB_*HP_; idx += nthr) {
        int n = idx / HP_, h = idx % HP_;
        float v = 0.f;
        if (h < H_) {
            v = bd[h];
            #pragma unroll
            for (int t = 0; t < DE_; t++)
                v += dist_emb[n * DE_ + t] * Wd[t * H_ + h];
        }
        dp[idx] = v;
    }
    for (int idx = tid; idx < D_*LRWP_; idx += nthr) {
        int k = idx / LRWP_, c = idx % LRWP_;
        float v = 0.f;
        if (c < H_) v = Wl[k * H_ + c];
        else if (c >= HP_ && c < HP_ + H_) v = Wr[k * H_ + (c - HP_)];
        wlr[idx] = rna(v);
    }
    for (int c = tid; c < LRWP_; c += nthr) {
        float v = 0.f;
        if (c < H_) v = bl[c];
        else if (c >= HP_ && c < HP_ + H_) v = br[c - HP_];
        blr[c] = v;
    }
}

// ---------------- tf32 GEMM (R8 config): 128 thr, 4 warps (2x2), 3-stage cp.async ----------------
#define ASTRIDE 36
#define BSTRIDE 72
template<int BM>
__global__ void __launch_bounds__(128, 2)
mma_gemm(const float* __restrict__ a0,
         const float* __restrict__ a1,
         const float* __restrict__ a2,
         const float* __restrict__ W,
         const float* __restrict__ bias,
         const float* __restrict__ rowscale,
         const float* __restrict__ e1,
         const float* __restrict__ e2,
         float* __restrict__ Cout,
         float* __restrict__ Ct,
         int M, int N, int K, int lda, int ldc,
         long sA, long sW, int bzmask, long sC, int sRS,
         int act, int roundOut)
{
    constexpr int MT = BM / 32;
    constexpr int ACH = (BM == 64) ? 4 : 2;
    constexpr int ASZ = BM * ASTRIDE;
    constexpr int BSZ = 32 * BSTRIDE;
    extern __shared__ unsigned dsm[];
    unsigned* Abase = dsm;
    unsigned* Bbase = dsm + 3 * ASZ;

    int z = blockIdx.z;
    a0 += (long)z * sA;
    W  += (long)(z & bzmask) * sW;
    Cout += (long)z * sC;
    if (rowscale) rowscale += (long)z * sRS;

    int tid = threadIdx.x;
    int warp = tid >> 5, lane = tid & 31;
    int m0 = blockIdx.y * BM, n0 = blockIdx.x * 64;
    int wm = (warp >> 1) * (BM / 2), wn = (warp & 1) * 32;

    auto issue = [&](int k0, int stage) {
        unsigned* As = Abase + stage * ASZ;
        unsigned* Bs = Bbase + stage * BSZ;
        int seg = k0 >> 10, col = k0 & 1023;
        const float* ap = (seg == 0) ? a0 : (seg == 1) ? a1 : a2;
        #pragma unroll
        for (int i = 0; i < ACH; i++) {
            int id = tid + i * 128;
            int row = id >> 3, c16 = (id & 7) * 4;
            cpa16(As + row * ASTRIDE + c16, ap + (long)(m0 + row) * lda + col + c16);
        }
        #pragma unroll
        for (int i = 0; i < 4; i++) {
            int id = tid + i * 128;
            int kr = id >> 4, c16 = (id & 15) * 4;
            cpa16(Bs + kr * BSTRIDE + c16, W + (long)(k0 + kr) * N + n0 + c16);
        }
        cp_commit();
    };

    int nt = K >> 5;
    issue(0, 0);
    issue(32, 1);

    float acc[MT][4][4];
    #pragma unroll
    for (int i = 0; i < MT; i++)
        #pragma unroll
        for (int j = 0; j < 4; j++)
            #pragma unroll
            for (int q = 0; q < 4; q++) acc[i][j][q] = 0.f;

    int stage = 0;
    for (int t = 0; t < nt; t++) {
        if (t == nt - 1) cp_wait<0>(); else cp_wait<1>();
        __syncthreads();
        if (t + 2 < nt) issue((t + 2) << 5, (stage + 2) % 3);

        unsigned* As = Abase + stage * ASZ;
        unsigned* Bs = Bbase + stage * BSZ;

        #pragma unroll
        for (int kx = 0; kx < 4; kx++) {
            unsigned a[MT][4];
            #pragma unroll
            for (int mt = 0; mt < MT; mt++) {
                int r_ = wm + mt * 16 + (lane >> 2);
                int c_ = kx * 8 + (lane & 3);
                a[mt][0] = As[r_ * ASTRIDE + c_];
                a[mt][1] = As[(r_ + 8) * ASTRIDE + c_];
                a[mt][2] = As[r_ * ASTRIDE + c_ + 4];
                a[mt][3] = As[(r_ + 8) * ASTRIDE + c_ + 4];
            }
            #pragma unroll
            for (int ct = 0; ct < 4; ct++) {
                unsigned b0 = Bs[(kx*8 + (lane & 3)) * BSTRIDE + wn + ct*8 + (lane >> 2)];
                unsigned b1 = Bs[(kx*8 + (lane & 3) + 4) * BSTRIDE + wn + ct*8 + (lane >> 2)];
                #pragma unroll
                for (int mt = 0; mt < MT; mt++) {
                    asm volatile(
                        "mma.sync.aligned.m16n8k8.row.col.f32.tf32.tf32.f32 "
                        "{%0,%1,%2,%3}, {%4,%5,%6,%7}, {%8,%9}, {%0,%1,%2,%3};"
                        : "+f"(acc[mt][ct][0]), "+f"(acc[mt][ct][1]),
                          "+f"(acc[mt][ct][2]), "+f"(acc[mt][ct][3])
                        : "r"(a[mt][0]), "r"(a[mt][1]), "r"(a[mt][2]), "r"(a[mt][3]),
                          "r"(b0), "r"(b1));
                }
            }
        }
        stage = (stage + 1) % 3;
    }

    #pragma unroll
    for (int mt = 0; mt < MT; mt++) {
        #pragma unroll
        for (int rh = 0; rh < 2; rh++) {
            int gm = m0 + wm + mt * 16 + (lane >> 2) + rh * 8;
            float rs = rowscale ? rowscale[gm] : 1.f;
            #pragma unroll
            for (int ct = 0; ct < 4; ct++) {
                int gn = n0 + wn + ct * 8 + (lane & 3) * 2;
                float v0 = acc[mt][ct][rh * 2 + 0];
                float v1 = acc[mt][ct][rh * 2 + 1];
                if (bias) { v0 += bias[gn]; v1 += bias[gn + 1]; }
                v0 *= rs; v1 *= rs;
                long off = (long)gm * ldc + gn;
                if (act == 1) { v0 = tanhf(v0); v1 = tanhf(v1); }
                else if (act == 2) {
                    v0 = 1.f / (1.f + expf(-v0));
                    v1 = 1.f / (1.f + expf(-v1));
                }
                else if (act == 3) {
                    float g0 = 1.f / (1.f + expf(-v0));
                    float g1 = 1.f / (1.f + expf(-v1));
                    v0 = g0 * e1[off]     + (1.f - g0) * e2[off];
                    v1 = g1 * e1[off + 1] + (1.f - g1) * e2[off + 1];
                }
                if (roundOut) { v0 = rna(v0); v1 = rna(v1); }
                *(float2*)(Cout + off) = make_float2(v0, v1);
                if (Ct) *(float2*)(Ct + off) = make_float2(rna(v0), rna(v1));
            }
        }
    }
}

// ---------------- TC scorer v5: 2 i's per block (halved LDG traffic) ----------------
#define SCOR_HSTRIDE 156
#define SCOR_SMEM_WORDS (2*NB_*HP_ + 2*(2*19*32) + 2*K_ + 16 + 8*16*SCOR_HSTRIDE)
__global__ void __launch_bounds__(256)
scorer_tc(const float* __restrict__ lr,
          const float* __restrict__ dp,
          const float* __restrict__ Wo,
          const float* __restrict__ bo,
          const int* __restrict__ span_begin,
          const int* __restrict__ span_end,
          float* __restrict__ scores,
          int first)
{
    extern __shared__ float sm[];
    float* s_t  = sm;                              // [2][NB][152]
    uint2* s_w2 = (uint2*)(sm + 2*NB_*HP_);        // [2][19][32]
    int*   s_bk = (int*)(s_w2 + 2*19*32);          // [2][384]
    float* s_bo = (float*)(s_bk + 2*K_);           // [16]
    float* s_h  = s_bo + 16;                       // [8][16][156]

    int i0 = blockIdx.x * 2, b = blockIdx.y;
    int tid = threadIdx.x;
    int warp = tid >> 5, lane = tid & 31;

    // t tables for both i's
    for (int x = tid; x < 2 * NB_ * HP_; x += 256) {
        int ii = x / (NB_ * HP_);
        int rem = x - ii * (NB_ * HP_);
        s_t[x] = rna(lr[(long)(b * K_ + i0 + ii) * LRWP_ + rem % HP_] + dp[rem]);
    }
    // Wo fragment tables
    for (int x = tid; x < 2 * 19 * 32; x += 256) {
        int ln = x & 31, kt = (x >> 5) % 19, nt = x / (19 * 32);
        int k0 = kt * 8 + (ln & 3), k1 = k0 + 4;
        int n  = nt * 8 + (ln >> 2);
        uint2 v;
        v.x = (k0 < H_ && n < L_) ? f2t(Wo[k0 * L_ + n]) : 0u;
        v.y = (k1 < H_ && n < L_) ? f2t(Wo[k1 * L_ + n]) : 0u;
        s_w2[x] = v;
    }
    // buckets for both i's
    for (int x = tid; x < 2 * K_; x += 256) {
        int ii = x / K_, j = x - ii * K_;
        int endi = span_end[b * K_ + i0 + ii];
        int d = span_begin[b * K_ + j] - endi;
        int da = d < 0 ? -d : d;
        int bk;
        if (da <= 4) bk = da;
        else {
            int lg = 31 - __clz(da) + 3;
            bk = lg < (NB_ - 1) ? lg : (NB_ - 1);
        }
        s_bk[x] = bk;
    }
    if (tid < 16) s_bo[tid] = (tid < L_) ? bo[tid] : 0.f;
    __syncthreads();

    float* hbase = s_h + warp * (16 * SCOR_HSTRIDE);
    const float* rbase = lr + (long)b * K_ * LRWP_ + HP_;
    int row = lane >> 1, half = lane & 1;
    int ar = lane >> 2, ac = lane & 3;
    int gc0 = (lane & 3) * 2;
    int gc1 = 8 + gc0;
    bool nt1ok = gc1 < L_;

    #pragma unroll
    for (int ii = 0; ii < 2; ii++) {
        long srow = (long)(b * K_ + i0 + ii) * K_;
        const int* bkp = s_bk + ii * K_;
        const float* tbase = s_t + ii * NB_ * HP_;

        #pragma unroll
        for (int s = 0; s < 3; s++) {
            int j0 = (s * 8 + warp) * 16;

            long o0 = (srow + j0 + ar) * L_ + gc0;
            float2 q00, q01, q10, q11;
            if (!first) {
                q00 = *(float2*)(scores + o0);
                q01 = *(float2*)(scores + o0 + 8 * L_);
                if (nt1ok) {
                    q10 = *(float2*)(scores + o0 + 8);
                    q11 = *(float2*)(scores + o0 + 8 * L_ + 8);
                }
            }

            // build private H tile
            {
                int j = j0 + row;
                const float* rr = rbase + (long)j * LRWP_ + half * 76;
                const float* tt = tbase + bkp[j] * HP_ + half * 76;
                float* hh = hbase + row * SCOR_HSTRIDE + half * 76;
                #pragma unroll
                for (int x = 0; x < 19; x++) {
                    float4 rv = *(const float4*)(rr + x * 4);
                    float4 tv = *(const float4*)(tt + x * 4);
                    float4 hv;
                    hv.x = rna(fmaxf(rv.x + tv.x, 0.f));
                    hv.y = rna(fmaxf(rv.y + tv.y, 0.f));
                    hv.z = rna(fmaxf(rv.z + tv.z, 0.f));
                    hv.w = rna(fmaxf(rv.w + tv.w, 0.f));
                    *(float4*)(hh + x * 4) = hv;
                }
            }
            __syncwarp();

            float acc0[2][4] = {{0.f,0.f,0.f,0.f},{0.f,0.f,0.f,0.f}};
            float acc1[2][4] = {{0.f,0.f,0.f,0.f},{0.f,0.f,0.f,0.f}};
            #pragma unroll
            for (int kt = 0; kt < 19; kt++) {
                int p = kt & 1;
                unsigned a0 = __float_as_uint(hbase[ar * SCOR_HSTRIDE + kt * 8 + ac]);
                unsigned a1 = __float_as_uint(hbase[(ar + 8) * SCOR_HSTRIDE + kt * 8 + ac]);
                unsigned a2 = __float_as_uint(hbase[ar * SCOR_HSTRIDE + kt * 8 + ac + 4]);
                unsigned a3 = __float_as_uint(hbase[(ar + 8) * SCOR_HSTRIDE + kt * 8 + ac + 4]);
                uint2 w0 = s_w2[kt * 32 + lane];
                uint2 w1 = s_w2[(19 + kt) * 32 + lane];
                asm volatile(
                    "mma.sync.aligned.m16n8k8.row.col.f32.tf32.tf32.f32 "
                    "{%0,%1,%2,%3}, {%4,%5,%6,%7}, {%8,%9}, {%0,%1,%2,%3};"
                    : "+f"(acc0[p][0]), "+f"(acc0[p][1]), "+f"(acc0[p][2]), "+f"(acc0[p][3])
                    : "r"(a0), "r"(a1), "r"(a2), "r"(a3), "r"(w0.x), "r"(w0.y));
                asm volatile(
                    "mma.sync.aligned.m16n8k8.row.col.f32.tf32.tf32.f32 "
                    "{%0,%1,%2,%3}, {%4,%5,%6,%7}, {%8,%9}, {%0,%1,%2,%3};"
                    : "+f"(acc1[p][0]), "+f"(acc1[p][1]), "+f"(acc1[p][2]), "+f"(acc1[p][3])
                    : "r"(a0), "r"(a1), "r"(a2), "r"(a3), "r"(w1.x), "r"(w1.y));
            }

            {
                float v0 = acc0[0][0] + acc0[1][0] + s_bo[gc0];
                float v1 = acc0[0][1] + acc0[1][1] + s_bo[gc0 + 1];
                float v2 = acc0[0][2] + acc0[1][2] + s_bo[gc0];
                float v3 = acc0[0][3] + acc0[1][3] + s_bo[gc0 + 1];
                if (!first) { v0 += q00.x; v1 += q00.y; v2 += q01.x; v3 += q01.y; }
                *(float2*)(scores + o0)          = make_float2(v0, v1);
                *(float2*)(scores + o0 + 8 * L_) = make_float2(v2, v3);
            }
            if (nt1ok) {
                float v0 = acc1[0][0] + acc1[1][0] + s_bo[gc1];
                float v1 = acc1[0][1] + acc1[1][1] + s_bo[gc1 + 1];
                float v2 = acc1[0][2] + acc1[1][2] + s_bo[gc1];
                float v3 = acc1[0][3] + acc1[1][3] + s_bo[gc1 + 1];
                if (!first) { v0 += q10.x; v1 += q10.y; v2 += q11.x; v3 += q11.y; }
                *(float2*)(scores + o0 + 8)          = make_float2(v0, v1);
                *(float2*)(scores + o0 + 8 * L_ + 8) = make_float2(v2, v3);
            }
            __syncwarp();
        }
    }
}

// ---------------- probs + row-sums fused ----------------
__global__ void probs_kernel(const float* __restrict__ scores,
                             const float* __restrict__ mask,
                             float* __restrict__ probsAll,
                             float* __restrict__ invAll)
{
    int i = blockIdx.x, b = blockIdx.y;
    float ssum = 0.f;
    for (int j = threadIdx.x; j < K_; j += blockDim.x) {
        const float* s = scores + (((long)(b * K_ + i)) * K_ + j) * L_;
        float m = s[0];
        #pragma unroll
        for (int c = 1; c < L_; c++) m = fmaxf(m, s[c]);
        float p = rna((1.f / (1.f + expf(-m))) * mask[((long)(b * K_ + i)) * K_ + j]);
        probsAll[((long)(b * K_ + i)) * K_ + j] = p;
        probsAll[(long)SZ_P + ((long)(b * K_ + j)) * K_ + i] = p;
        ssum += p;
    }
    __shared__ float red[4];
    #pragma unroll
    for (int o = 16; o > 0; o >>= 1) ssum += __shfl_down_sync(0xffffffffu, ssum, o);
    int wid = threadIdx.x >> 5;
    if ((threadIdx.x & 31) == 0) red[wid] = ssum;
    __syncthreads();
    if (threadIdx.x == 0)
        invAll[b * K_ + i] = 1.f / (red[0] + red[1] + red[2] + red[3] + 1e-7f);
}

// ---------------- inverse column sums (probsT rows) ----------------
__global__ void invsum_kernel(const float* __restrict__ probsAll,
                              float* __restrict__ invAll)
{
    int row = blockIdx.x;
    const float* src = probsAll + (long)SZ_P + (long)row * K_;
    float s = 0.f;
    for (int j = threadIdx.x; j < K_; j += blockDim.x) s += src[j];
    __shared__ float red[4];
    #pragma unroll
    for (int o = 16; o > 0; o >>= 1) s += __shfl_down_sync(0xffffffffu, s, o);
    int wid = threadIdx.x >> 5;
    if ((threadIdx.x & 31) == 0) red[wid] = s;
    __syncthreads();
    if (threadIdx.x == 0)
        invAll[SZ_S + row] = 1.f / (red[0] + red[1] + red[2] + red[3] + 1e-7f);
}

// ---------------- scatter (last-write-wins) ----------------
__global__ void scatter_kernel(const float* __restrict__ u,
                               const float* __restrict__ all_span,
                               const int* __restrict__ prune,
                               const int* __restrict__ span_len,
                               float* __restrict__ out_all)
{
    int bk = blockIdx.x;
    int b = bk / K_, k = bk % K_;
    int idx = prune[bk];
    bool last = (k == K_ - 1) || (prune[bk + 1] != idx);
    if (!last) return;
    bool valid = k < span_len[b];
    const float* src = valid ? (u + (long)bk * D_)
                             : (all_span + ((long)b * N_ + idx) * D_);
    float* dst = out_all + ((long)b * N_ + idx) * D_;
    int t = threadIdx.x;
    float4 v = *(const float4*)(src + t * 4);
    *(float4*)(dst + t * 4) = v;
}

// ---------------- host orchestration ----------------
extern "C" void kernel_launch(void* const* d_in, const int* in_sizes, int n_in,
                              void* d_out, int out_size)
{
    const float* span_vecs  = (const float*)d_in[0];
    const float* all_span   = (const float*)d_in[1];
    const int*   span_begin = (const int*)  d_in[2];
    const int*   span_end   = (const int*)  d_in[3];
    const float* mask       = (const float*)d_in[4];
    const int*   prune      = (const int*)  d_in[5];
    const int*   span_len   = (const int*)  d_in[6];
    const float* Wl  = (const float*)d_in[8];
    const float* bl  = (const float*)d_in[9];
    const float* Wr  = (const float*)d_in[10];
    const float* br  = (const float*)d_in[11];
    const float* de  = (const float*)d_in[12];
    const float* Wd  = (const float*)d_in[13];
    const float* bd  = (const float*)d_in[14];
    const float* Wo  = (const float*)d_in[15];
    const float* bo  = (const float*)d_in[16];
    const float* Wff1= (const float*)d_in[17];
    const float* Wff2= (const float*)d_in[18];
    const float* Wg  = (const float*)d_in[19];
    const float* bg  = (const float*)d_in[20];

    float *u, *u2, *ut, *ut2, *lr, *wlr, *blr, *dp, *probsAll, *invAll, *c, *tmp, *ctxt;
    float *wff1t, *wff2t, *wgt;
    cudaGetSymbolAddress((void**)&u,        g_u);
    cudaGetSymbolAddress((void**)&u2,       g_u2);
    cudaGetSymbolAddress((void**)&ut,       g_ut);
    cudaGetSymbolAddress((void**)&ut2,      g_ut2);
    cudaGetSymbolAddress((void**)&lr,       g_lr);
    cudaGetSymbolAddress((void**)&wlr,      g_wlr);
    cudaGetSymbolAddress((void**)&blr,      g_blr);
    cudaGetSymbolAddress((void**)&dp,       g_dp);
    cudaGetSymbolAddress((void**)&probsAll, g_probs);
    cudaGetSymbolAddress((void**)&invAll,   g_inv);
    cudaGetSymbolAddress((void**)&c,        g_c);
    cudaGetSymbolAddress((void**)&tmp,      g_tmp);
    cudaGetSymbolAddress((void**)&ctxt,     g_ctxt);
    cudaGetSymbolAddress((void**)&wff1t,    g_wff1t);
    cudaGetSymbolAddress((void**)&wff2t,    g_wff2t);
    cudaGetSymbolAddress((void**)&wgt,      g_wgt);

    float* out_all = (float*)d_out;
    float* out_u   = out_all + (size_t)B_ * N_ * D_;
    float* out_sc  = out_u   + (size_t)B_ * K_ * D_;

    const int M = B_ * K_;

    const int smem64 = 3 * (64 * ASTRIDE + 32 * BSTRIDE) * 4;
    const int smem32 = 3 * (32 * ASTRIDE + 32 * BSTRIDE) * 4;
    const int smemSc = SCOR_SMEM_WORDS * 4;  // ~105KB
    cudaFuncSetAttribute(mma_gemm<64>, cudaFuncAttributeMaxDynamicSharedMemorySize, smem64);
    cudaFuncSetAttribute(scorer_tc, cudaFuncAttributeMaxDynamicSharedMemorySize, smemSc);

    convert_kernel<<<148, 256>>>(Wff1, Wff2, Wg, span_vecs, wff1t, wff2t, wgt, u, ut);
    init_kernel<<<128, 256>>>(de, Wd, bd, Wl, bl, Wr, br, dp, wlr, blr);

    float *ucur = u,  *unext = u2;
    float *utcur = ut, *utnext = ut2;

    mma_gemm<32><<<dim3(6, 24, 1), 128, smem32>>>(utcur, utcur, utcur, wlr, blr, nullptr, nullptr, nullptr,
                                                  lr, nullptr, M, LRWP_, D_, D_, LRWP_, 0, 0, 0, 0, 0, 0, 0);
    scorer_tc<<<dim3(K_ / 2, B_), 256, smemSc>>>(lr, dp, Wo, bo, span_begin, span_end, out_sc, 1);

    for (int it = 0; it < 2; it++) {
        probs_kernel<<<dim3(K_, B_), 128>>>(out_sc, mask, probsAll, invAll);
        invsum_kernel<<<B_ * K_, 128>>>(probsAll, invAll);

        mma_gemm<64><<<dim3(16, 6, 4), 128, smem64>>>(probsAll, probsAll, probsAll, utcur, nullptr, invAll,
                                                      nullptr, nullptr, c, nullptr,
                                                      K_, D_, K_, K_, D_,
                                                      (long)K_*K_, (long)K_*D_, 1, (long)K_*D_, K_, 0, 1);

        mma_gemm<64><<<dim3(16, 12, 1), 128, smem64>>>(utcur, c, c + SZ_U, wff1t, nullptr, nullptr,
                                                       nullptr, nullptr, tmp, nullptr,
                                                       M, D_, 3 * D_, D_, D_, 0, 0, 0, 0, 0, 1, 1);
        mma_gemm<64><<<dim3(16, 12, 1), 128, smem64>>>(tmp, tmp, tmp, wff2t, nullptr, nullptr,
                                                       nullptr, nullptr, ctxt, nullptr,
                                                       M, D_, D_, D_, D_, 0, 0, 0, 0, 0, 0, 1);
        mma_gemm<64><<<dim3(16, 12, 1), 128, smem64>>>(utcur, ctxt, ctxt, wgt, bg, nullptr,
                                                       ucur, ctxt, unext, utnext,
                                                       M, D_, 2 * D_, D_, D_, 0, 0, 0, 0, 0, 3, 0);
        float* s1 = ucur; ucur = unext; unext = s1;
        float* s2 = utcur; utcur = utnext; utnext = s2;

        mma_gemm<32><<<dim3(6, 24, 1), 128, smem32>>>(utcur, utcur, utcur, wlr, blr, nullptr, nullptr, nullptr,
                                                      lr, nullptr, M, LRWP_, D_, D_, LRWP_, 0, 0, 0, 0, 0, 0, 0);
        scorer_tc<<<dim3(K_ / 2, B_), 256, smemSc>>>(lr, dp, Wo, bo, span_begin, span_end, out_sc, 0);
    }

    cudaMemcpyAsync(out_all, all_span, sizeof(float) * (size_t)B_ * N_ * D_, cudaMemcpyDeviceToDevice);
    scatter_kernel<<<B_ * K_, 256>>>(ucur, all_span, prune, span_len, out_all);
    cudaMemcpyAsync(out_u, ucur, sizeof(float) * SZ_U, cudaMemcpyDeviceToDevice);
}